// round 10
// baseline (speedup 1.0000x reference)
#include <cuda_runtime.h>

// Math collapse (verified R8/R9): softmax over a size-1 axis == 1.0 exactly, so
//   out[b,c,f] = sum_t x[b,t,f]     (context/W/b are dead inputs).
//
// R9 falsified the occupancy theory (occ 74.7%, DRAM still 38%). Both prior
// kernels used narrow column-strip access (64-256B wide, 2KB stride).
// This round: two-kernel split where EVERY warp memory op is 512B contiguous:
//   K1: streaming reduce   x[b, 16-row chunk, :]  -> partials (2MB scratch)
//   K2: streaming broadcast partials -> out[b, 8-row chunk, :]
// Read phase and write phase are direction-separated (no R/W mixing).

#define B_ 32
#define T_ 512
#define C_ 256
#define F_ 512

static constexpr int F4       = F_ / 4;     // 128 float4 per row
static constexpr int TPB      = 256;
static constexpr int T_CHUNK  = 16;         // rows per K1 CTA
static constexpr int NCHUNK   = T_ / T_CHUNK;  // 32
static constexpr int C_CHUNK  = 8;          // rows per K2 CTA
static constexpr int NCCHUNK  = C_ / C_CHUNK; // 32

// Partial sums: [B][NCHUNK][F4] float4  (32*32*128*16B = 2MB scratch)
__device__ float4 g_part[B_ * NCHUNK * F4];

__device__ __forceinline__ void f4add(float4& a, const float4& b) {
    a.x += b.x; a.y += b.y; a.z += b.z; a.w += b.w;
}

// ---------------- K1: streaming T-reduction -------------------------------
// CTA (b, chunk) reads rows [chunk*16, chunk*16+16) of x[b] — a contiguous
// 32KB block. Thread layout: f4 = tid&127 (warp lanes consecutive -> each
// LDG.128 is 512B of consecutive addresses), rh = tid>>7 covers row parity.
__global__ __launch_bounds__(TPB)
void k1_reduce(const float* __restrict__ x) {
    const int b     = blockIdx.x >> 5;       // /NCHUNK
    const int chunk = blockIdx.x & 31;
    const int f4l   = threadIdx.x & (F4 - 1);
    const int rh    = threadIdx.x >> 7;       // 0 or 1

    const float4* xb = reinterpret_cast<const float4*>(x)
                     + ((size_t)b * T_ + chunk * T_CHUNK + rh) * F4 + f4l;

    // 8 independent loads (rows rh, rh+2, ..., rh+14), fully batched.
    float4 v0 = __ldg(&xb[ 0 * F4]);
    float4 v1 = __ldg(&xb[ 2 * F4]);
    float4 v2 = __ldg(&xb[ 4 * F4]);
    float4 v3 = __ldg(&xb[ 6 * F4]);
    float4 v4 = __ldg(&xb[ 8 * F4]);
    float4 v5 = __ldg(&xb[10 * F4]);
    float4 v6 = __ldg(&xb[12 * F4]);
    float4 v7 = __ldg(&xb[14 * F4]);
    f4add(v0, v4); f4add(v1, v5); f4add(v2, v6); f4add(v3, v7);
    f4add(v0, v2); f4add(v1, v3);
    f4add(v0, v1);

    __shared__ float4 sm[TPB];
    sm[threadIdx.x] = v0;
    __syncthreads();
    if (threadIdx.x < F4) {
        float4 tot = sm[threadIdx.x];
        f4add(tot, sm[threadIdx.x + F4]);
        // contiguous 2KB partial store per CTA
        g_part[((size_t)b * NCHUNK + chunk) * F4 + threadIdx.x] = tot;
    }
}

// ---------------- K2: sum partials + streaming broadcast ------------------
// CTA (b, cc) writes out[b, cc*8 .. cc*8+8, :] — a contiguous 16KB block.
__global__ __launch_bounds__(TPB)
void k2_broadcast(float* __restrict__ out) {
    const int b  = blockIdx.x >> 5;          // /NCCHUNK
    const int cc = blockIdx.x & 31;
    const int f4l = threadIdx.x & (F4 - 1);
    const int h   = threadIdx.x >> 7;        // 0/1: each half sums 16 chunks

    const float4* pb = &g_part[(size_t)b * NCHUNK * F4 + f4l];
    float4 s = make_float4(0.f, 0.f, 0.f, 0.f);
#pragma unroll
    for (int k = 0; k < NCHUNK / 2; ++k) {
        float4 v = __ldg(&pb[(size_t)(h * (NCHUNK / 2) + k) * F4]);
        f4add(s, v);
    }

    __shared__ float4 sm[TPB];
    sm[threadIdx.x] = s;
    __syncthreads();
    if (threadIdx.x < F4) {
        float4 tot = sm[threadIdx.x];
        f4add(tot, sm[threadIdx.x + F4]);
        sm[threadIdx.x] = tot;               // final column sum for (b, f4)
    }
    __syncthreads();

    // 8 rows x 128 float4 = 1024 stores; 4 per thread, warp-contiguous 512B.
    float4* ob = reinterpret_cast<float4*>(out)
               + ((size_t)b * C_ + cc * C_CHUNK) * F4;
#pragma unroll
    for (int k = 0; k < (C_CHUNK * F4) / TPB; ++k) {
        const int idx = (k << 8) + threadIdx.x;   // 0..1023, consecutive
        ob[idx] = sm[idx & (F4 - 1)];
    }
}

extern "C" void kernel_launch(void* const* d_in, const int* in_sizes, int n_in,
                              void* d_out, int out_size) {
    (void)in_sizes; (void)n_in; (void)out_size;
    const float* x = (const float*)d_in[0];   // [B,T,F]; context/W/b dead
    float* out = (float*)d_out;               // [B,C,F]
    k1_reduce<<<B_ * NCHUNK, TPB>>>(x);
    k2_broadcast<<<B_ * NCCHUNK, TPB>>>(out);
}